// round 4
// baseline (speedup 1.0000x reference)
#include <cuda_runtime.h>
#include <cuda_bf16.h>
#include <cstdint>

// ---------------------------------------------------------------------------
// GCNEncoder: 2-layer GCN, N=100000, E=3200000, 128 -> 32 -> 16.
//
// R3 changes vs R2:
//  * k_gemm1 was smem-crossbar bound (2 LDS / FMA, L1=84.7%). Now register-
//    tiled: warp = 4 nodes x 32 feats, k-unroll 4 -> 0.5 LDS / FMA, FMA-bound.
//  * Atomic RED scatters replaced by one-time CSR build + atomic-free
//    warp-per-node gather aggregation (coalesced 128B row reads, L2-resident
//    feature tables, sequential-FADD accumulation, coalesced stores).
//  * Layer-2 aggregation fuses the dinv*acc + b2 epilogue, writes d_out.
// ---------------------------------------------------------------------------

#define N_NODES 100000
#define N_EDGES 3200000
#define IN_C    128
#define HID     32
#define OUT_C   16

// Scratch (no cudaMalloc allowed) ------------------------------------------
__device__ int   g_degi[N_NODES];          // in-degree histogram (int)
__device__ int   g_off [N_NODES + 1];      // CSR offsets
__device__ int   g_cnt [N_NODES];          // fill cursors
__device__ int   g_csr [N_EDGES];          // CSR: source node per slot
__device__ float g_dinv[N_NODES];
__device__ float g_g1  [N_NODES * HID];    // dinv * (x @ W1)
__device__ float g_acc1[N_NODES * HID];    // layer-1 aggregation
__device__ float g_g2  [N_NODES * OUT_C];  // dinv * (relu(...) @ W2)
__device__ int   g_is64;                   // edge_index dtype flag

// edge_index accessors: layout [2, E]; row = [0:E), col = [E:2E).
__device__ __forceinline__ int edge_row(const void* ei, int e, int is64) {
    return is64 ? (int)((const long long*)ei)[e] : ((const int*)ei)[e];
}
__device__ __forceinline__ int edge_col(const void* ei, int e, int is64) {
    return is64 ? (int)((const long long*)ei)[(size_t)N_EDGES + e]
                : ((const int*)ei)[(size_t)N_EDGES + e];
}

// K0: dtype detection (int64 read of real int32 data combines two random
// values -> out of [0,N) with overwhelming probability over 2048 samples).
__global__ void k_detect(const void* __restrict__ ei) {
    __shared__ int bad;
    if (threadIdx.x == 0) bad = 0;
    __syncthreads();
    const long long* p = (const long long*)ei;
    for (int i = threadIdx.x; i < 2048; i += blockDim.x) {
        long long v = p[i];
        if (v < 0 || v >= N_NODES) atomicOr(&bad, 1);
    }
    __syncthreads();
    if (threadIdx.x == 0) g_is64 = (bad == 0) ? 1 : 0;
}

// K1: integer in-degree histogram over col.
__global__ void k_deg(const void* __restrict__ ei) {
    int t = blockIdx.x * blockDim.x + threadIdx.x;
    if (t >= N_EDGES) return;
    atomicAdd(&g_degi[edge_col(ei, t, g_is64)], 1);
}

// K2: single-block exclusive scan -> CSR offsets; also computes dinv.
__global__ __launch_bounds__(1024) void k_scan() {
    __shared__ int ssum[1024];
    const int CH = (N_NODES + 1023) / 1024;  // 98
    int t = threadIdx.x;
    int begin = t * CH;
    int end   = begin + CH; if (end > N_NODES) end = N_NODES;
    if (begin > N_NODES) begin = N_NODES;

    int s = 0;
    for (int i = begin; i < end; i++) s += g_degi[i];
    ssum[t] = s;
    __syncthreads();
    // inclusive Hillis-Steele scan over 1024
    for (int off = 1; off < 1024; off <<= 1) {
        int v = (t >= off) ? ssum[t - off] : 0;
        __syncthreads();
        ssum[t] += v;
        __syncthreads();
    }
    int run = (t == 0) ? 0 : ssum[t - 1];  // exclusive prefix
    for (int i = begin; i < end; i++) {
        int d = g_degi[i];
        g_off[i]  = run;
        g_dinv[i] = (d > 0) ? rsqrtf((float)d) : 0.0f;
        run += d;
    }
    if (t == 1023) g_off[N_NODES] = run;
}

// K3: CSR fill — slot via per-node cursor; neighbor order is arbitrary.
__global__ void k_fill(const void* __restrict__ ei) {
    int t = blockIdx.x * blockDim.x + threadIdx.x;
    if (t >= N_EDGES) return;
    int is64 = g_is64;
    int r = edge_row(ei, t, is64);
    int c = edge_col(ei, t, is64);
    int pos = g_off[c] + atomicAdd(&g_cnt[c], 1);
    g_csr[pos] = r;
}

// K4: g1[i][:] = dinv[i] * (x[i] @ W1).
// Register-tiled: warp = 4 nodes x 32 features, 4 acc/thread, k-unroll 4.
// Per step: 4 LDS.128 (x broadcast) + 4 LDS.32 (W) = 8 wavefronts / 16 FFMA.
__global__ __launch_bounds__(256) void k_gemm1(const float* __restrict__ x,
                                               const float* __restrict__ W1) {
    __shared__ float sW[IN_C * HID];    // 16KB, [k][j]
    __shared__ float sx[32][IN_C];      // 16KB, 32 nodes/block
    int tid = threadIdx.x;
#pragma unroll
    for (int i = tid; i < (IN_C * HID) / 4; i += 256)
        ((float4*)sW)[i] = ((const float4*)W1)[i];

    int nb = blockIdx.x * 32;           // 100000 / 32 = 3125 blocks exactly
#pragma unroll
    for (int i = tid; i < 32 * (IN_C / 4); i += 256) {
        int row = i >> 5, c4 = i & 31;  // 32 float4 per row
        ((float4*)sx[row])[c4] =
            ((const float4*)(x + (size_t)(nb + row) * IN_C))[c4];
    }
    __syncthreads();

    int warp = tid >> 5, lane = tid & 31;
    int n0 = warp * 4;
    float a0 = 0.f, a1 = 0.f, a2 = 0.f, a3 = 0.f;
#pragma unroll 4
    for (int kk = 0; kk < IN_C; kk += 4) {
        float4 xa = *(const float4*)&sx[n0 + 0][kk];
        float4 xb = *(const float4*)&sx[n0 + 1][kk];
        float4 xc = *(const float4*)&sx[n0 + 2][kk];
        float4 xd = *(const float4*)&sx[n0 + 3][kk];
        float w0 = sW[(kk + 0) * HID + lane];
        float w1 = sW[(kk + 1) * HID + lane];
        float w2 = sW[(kk + 2) * HID + lane];
        float w3 = sW[(kk + 3) * HID + lane];
        a0 = fmaf(xa.x, w0, fmaf(xa.y, w1, fmaf(xa.z, w2, fmaf(xa.w, w3, a0))));
        a1 = fmaf(xb.x, w0, fmaf(xb.y, w1, fmaf(xb.z, w2, fmaf(xb.w, w3, a1))));
        a2 = fmaf(xc.x, w0, fmaf(xc.y, w1, fmaf(xc.z, w2, fmaf(xc.w, w3, a2))));
        a3 = fmaf(xd.x, w0, fmaf(xd.y, w1, fmaf(xd.z, w2, fmaf(xd.w, w3, a3))));
    }
    g_g1[(size_t)(nb + n0 + 0) * HID + lane] = a0 * g_dinv[nb + n0 + 0];
    g_g1[(size_t)(nb + n0 + 1) * HID + lane] = a1 * g_dinv[nb + n0 + 1];
    g_g1[(size_t)(nb + n0 + 2) * HID + lane] = a2 * g_dinv[nb + n0 + 2];
    g_g1[(size_t)(nb + n0 + 3) * HID + lane] = a3 * g_dinv[nb + n0 + 3];
}

// K5: layer-1 aggregation, atomic-free. Warp per node, lane = feature.
// Edge ids staged coalesced (32/warp) then broadcast via shfl; dual
// accumulators break the FADD dependence chain.
__global__ __launch_bounds__(256) void k_agg1() {
    int gw   = (blockIdx.x * 256 + threadIdx.x) >> 5;
    int lane = threadIdx.x & 31;
    if (gw >= N_NODES) return;
    int s = g_off[gw], e = g_off[gw + 1];
    float acc0 = 0.f, acc1 = 0.f;
    for (int base = s; base < e; base += 32) {
        int n = e - base; if (n > 32) n = 32;
        int r = g_csr[base + ((lane < n) ? lane : 0)];
        for (int j = 0; j + 1 < n; j += 2) {
            int r0 = __shfl_sync(0xffffffffu, r, j);
            int r1 = __shfl_sync(0xffffffffu, r, j + 1);
            acc0 += g_g1[(size_t)r0 * HID + lane];
            acc1 += g_g1[(size_t)r1 * HID + lane];
        }
        if (n & 1) {
            int r0 = __shfl_sync(0xffffffffu, r, n - 1);
            acc0 += g_g1[(size_t)r0 * HID + lane];
        }
    }
    g_acc1[(size_t)gw * HID + lane] = acc0 + acc1;
}

// K6: h = relu(acc1*dinv + b1); g2 = dinv * (h @ W2). Warp per node.
__global__ __launch_bounds__(256) void k_fuse(const float* __restrict__ W2,
                                              const float* __restrict__ b1) {
    __shared__ float sW[HID * OUT_C];
    __shared__ float sb1[HID];
    __shared__ float sh[8][HID];
    for (int i = threadIdx.x; i < HID * OUT_C; i += 256) sW[i] = W2[i];
    for (int i = threadIdx.x; i < HID; i += 256) sb1[i] = b1[i];
    __syncthreads();

    int warp = threadIdx.x >> 5, lane = threadIdx.x & 31;
    int node = blockIdx.x * 8 + warp;
    if (node >= N_NODES) return;

    float dv = g_dinv[node];
    float h = fmaxf(g_acc1[(size_t)node * HID + lane] * dv + sb1[lane], 0.0f);
    sh[warp][lane] = h;
    __syncwarp();

    if (lane < OUT_C) {
        float acc = 0.0f;
#pragma unroll
        for (int k = 0; k < HID; k++)
            acc = fmaf(sh[warp][k], sW[k * OUT_C + lane], acc);
        g_g2[(size_t)node * OUT_C + lane] = acc * dv;
    }
}

// K7: layer-2 aggregation + fused epilogue, writes d_out directly.
// Warp per node; half-warps process even/odd edges (16-feature rows),
// cross-half combine via shfl.
__global__ __launch_bounds__(256) void k_agg2(float* __restrict__ out,
                                              const float* __restrict__ b2) {
    int gw   = (blockIdx.x * 256 + threadIdx.x) >> 5;
    int lane = threadIdx.x & 31;
    if (gw >= N_NODES) return;
    int half = lane >> 4, l = lane & 15;
    int s = g_off[gw], e = g_off[gw + 1];
    float acc = 0.f;
    for (int base = s; base < e; base += 32) {
        int n = e - base; if (n > 32) n = 32;
        int r = g_csr[base + ((lane < n) ? lane : 0)];
        for (int jj = 0; jj < n; jj += 2) {        // uniform trip count
            int j = jj + half;
            int rj = __shfl_sync(0xffffffffu, r, (j < n) ? j : 0);
            if (j < n) acc += g_g2[(size_t)rj * OUT_C + l];
        }
    }
    acc += __shfl_down_sync(0xffffffffu, acc, 16);
    if (half == 0)
        out[(size_t)gw * OUT_C + l] = acc * g_dinv[gw] + b2[l];
}

// K8: zero any tail of d_out beyond N*OUT_C (tuple scalar slot).
__global__ void k_tail(float* __restrict__ out, int out_size) {
    int t = N_NODES * OUT_C + blockIdx.x * blockDim.x + threadIdx.x;
    if (t < out_size) out[t] = 0.0f;
}

// ---------------------------------------------------------------------------
extern "C" void kernel_launch(void* const* d_in, const int* in_sizes, int n_in,
                              void* d_out, int out_size) {
    const float* x  = (const float*)d_in[0];
    const void*  ei = d_in[1];
    const float* W1 = (const float*)d_in[2];
    const float* b1 = (const float*)d_in[3];
    const float* W2 = (const float*)d_in[4];
    const float* b2 = (const float*)d_in[5];
    float* out = (float*)d_out;

    void *p_degi, *p_cnt;
    cudaGetSymbolAddress(&p_degi, g_degi);
    cudaGetSymbolAddress(&p_cnt,  g_cnt);
    cudaMemsetAsync(p_degi, 0, (size_t)N_NODES * sizeof(int));
    cudaMemsetAsync(p_cnt,  0, (size_t)N_NODES * sizeof(int));

    k_detect<<<1, 256>>>(ei);
    k_deg  <<<(N_EDGES + 255) / 256, 256>>>(ei);
    k_scan <<<1, 1024>>>();
    k_fill <<<(N_EDGES + 255) / 256, 256>>>(ei);
    k_gemm1<<<N_NODES / 32, 256>>>(x, W1);               // 3125 blocks
    k_agg1 <<<(N_NODES * 32 + 255) / 256, 256>>>();
    k_fuse <<<(N_NODES + 7) / 8, 256>>>(W2, b1);
    k_agg2 <<<(N_NODES * 32 + 255) / 256, 256>>>(out, b2);

    int tail = out_size - N_NODES * OUT_C;
    if (tail > 0)
        k_tail<<<(tail + 255) / 256, 256>>>(out, out_size);
}

// round 5
// speedup vs baseline: 1.7177x; 1.7177x over previous
#include <cuda_runtime.h>
#include <cuda_bf16.h>
#include <cstdint>

// ---------------------------------------------------------------------------
// GCNEncoder: 2-layer GCN, N=100000, E=3200000, 128 -> 32 -> 16.
//
// R4: revert edge phase to R2's RED-scatter design (R3's CSR gather was
// L2-latency bound and the CSR build cost ~100us). Keep R3's register-tiled
// GEMM. New: fuse degree histogram + int32 index decode INTO the GEMM kernel
// as extra blocks (disjoint pipes -> overlap), then scale g1 by dinv after.
// ---------------------------------------------------------------------------

#define N_NODES 100000
#define N_EDGES 3200000
#define IN_C    128
#define HID     32
#define OUT_C   16

#define GEMM_BLOCKS (N_NODES / 32)              // 3125
#define DEG_BLOCKS  (N_EDGES / 256)             // 12500

// Scratch (no cudaMalloc allowed) ------------------------------------------
__device__ int   g_degi[N_NODES];          // in-degree histogram
__device__ int   g_row [N_EDGES];          // decoded int32 indices
__device__ int   g_col [N_EDGES];
__device__ float g_dinv[N_NODES];
__device__ float g_g1  [N_NODES * HID];    // x@W1, then scaled by dinv
__device__ float g_acc1[N_NODES * HID];    // layer-1 scatter accumulator
__device__ float g_g2  [N_NODES * OUT_C];  // dinv * (relu(...) @ W2)
__device__ float g_acc2[N_NODES * OUT_C];  // layer-2 scatter accumulator
__device__ int   g_is64;                   // edge_index dtype flag

__device__ __forceinline__ int edge_row(const void* ei, int e, int is64) {
    return is64 ? (int)((const long long*)ei)[e] : ((const int*)ei)[e];
}
__device__ __forceinline__ int edge_col(const void* ei, int e, int is64) {
    return is64 ? (int)((const long long*)ei)[(size_t)N_EDGES + e]
                : ((const int*)ei)[(size_t)N_EDGES + e];
}

// K0: dtype detection (reading genuine int32 data as int64 combines two
// random values in [0,1e5) -> out of range with overwhelming probability).
__global__ void k_detect(const void* __restrict__ ei) {
    __shared__ int bad;
    if (threadIdx.x == 0) bad = 0;
    __syncthreads();
    const long long* p = (const long long*)ei;
    for (int i = threadIdx.x; i < 2048; i += blockDim.x) {
        long long v = p[i];
        if (v < 0 || v >= N_NODES) atomicOr(&bad, 1);
    }
    __syncthreads();
    if (threadIdx.x == 0) g_is64 = (bad == 0) ? 1 : 0;
}

// K1 (fused): blocks [0, GEMM_BLOCKS) compute g1 = x @ W1 (unscaled,
// register-tiled, FMA-bound). Blocks [GEMM_BLOCKS, +DEG_BLOCKS) decode edge
// indices to int32 and build the degree histogram (memory/atomic-bound).
// Disjoint pipes -> the two phases overlap across the chip.
__global__ __launch_bounds__(256) void k_fusedA(const float* __restrict__ x,
                                                const float* __restrict__ W1,
                                                const void*  __restrict__ ei) {
    int tid = threadIdx.x;
    if (blockIdx.x >= GEMM_BLOCKS) {
        // ---- degree + decode ----
        int e = (blockIdx.x - GEMM_BLOCKS) * 256 + tid;   // exact: E = 12500*256
        int is64 = g_is64;
        int r = edge_row(ei, e, is64);
        int c = edge_col(ei, e, is64);
        g_row[e] = r;
        g_col[e] = c;
        atomicAdd(&g_degi[c], 1);
        return;
    }
    // ---- register-tiled GEMM: warp = 4 nodes x 32 features ----
    __shared__ float sW[IN_C * HID];    // 16KB, [k][j]
    __shared__ float sx[32][IN_C];      // 16KB
#pragma unroll
    for (int i = tid; i < (IN_C * HID) / 4; i += 256)
        ((float4*)sW)[i] = ((const float4*)W1)[i];

    int nb = blockIdx.x * 32;
#pragma unroll
    for (int i = tid; i < 32 * (IN_C / 4); i += 256) {
        int row = i >> 5, c4 = i & 31;
        ((float4*)sx[row])[c4] =
            ((const float4*)(x + (size_t)(nb + row) * IN_C))[c4];
    }
    __syncthreads();

    int warp = tid >> 5, lane = tid & 31;
    int n0 = warp * 4;
    float a0 = 0.f, a1 = 0.f, a2 = 0.f, a3 = 0.f;
#pragma unroll 4
    for (int kk = 0; kk < IN_C; kk += 4) {
        float4 xa = *(const float4*)&sx[n0 + 0][kk];
        float4 xb = *(const float4*)&sx[n0 + 1][kk];
        float4 xc = *(const float4*)&sx[n0 + 2][kk];
        float4 xd = *(const float4*)&sx[n0 + 3][kk];
        float w0 = sW[(kk + 0) * HID + lane];
        float w1 = sW[(kk + 1) * HID + lane];
        float w2 = sW[(kk + 2) * HID + lane];
        float w3 = sW[(kk + 3) * HID + lane];
        a0 = fmaf(xa.x, w0, fmaf(xa.y, w1, fmaf(xa.z, w2, fmaf(xa.w, w3, a0))));
        a1 = fmaf(xb.x, w0, fmaf(xb.y, w1, fmaf(xb.z, w2, fmaf(xb.w, w3, a1))));
        a2 = fmaf(xc.x, w0, fmaf(xc.y, w1, fmaf(xc.z, w2, fmaf(xc.w, w3, a2))));
        a3 = fmaf(xd.x, w0, fmaf(xd.y, w1, fmaf(xd.z, w2, fmaf(xd.w, w3, a3))));
    }
    g_g1[(size_t)(nb + n0 + 0) * HID + lane] = a0;
    g_g1[(size_t)(nb + n0 + 1) * HID + lane] = a1;
    g_g1[(size_t)(nb + n0 + 2) * HID + lane] = a2;
    g_g1[(size_t)(nb + n0 + 3) * HID + lane] = a3;
}

// K2: dinv = rsqrt(deg) (or 0); scale g1 rows in place.
__global__ void k_scale() {
    int t = blockIdx.x * blockDim.x + threadIdx.x;
    if (t >= N_NODES * HID) return;
    int node = t >> 5;                      // HID == 32
    int d = g_degi[node];                   // broadcast within warp
    float dv = (d > 0) ? rsqrtf((float)d) : 0.0f;
    g_g1[t] *= dv;
    if ((t & 31) == 0) g_dinv[node] = dv;
}

// K3: layer-1 scatter. 8 threads/edge, float4 gather + red.v4.f32.
__global__ __launch_bounds__(256) void k_scat1() {
    int t = blockIdx.x * blockDim.x + threadIdx.x;
    if (t >= N_EDGES * 8) return;
    int e = t >> 3, q = t & 7;
    int r = g_row[e];                       // L1 broadcast among 8 threads
    int c = g_col[e];
    const float4 v = *(const float4*)(g_g1 + (size_t)r * HID + q * 4);
    float* dst = g_acc1 + (size_t)c * HID + q * 4;
    asm volatile("red.global.add.v4.f32 [%0], {%1,%2,%3,%4};"
                 :: "l"(dst), "f"(v.x), "f"(v.y), "f"(v.z), "f"(v.w) : "memory");
}

// K4: h = relu(acc1*dinv + b1); g2 = dinv * (h @ W2). Warp per node.
__global__ __launch_bounds__(256) void k_fuse(const float* __restrict__ W2,
                                              const float* __restrict__ b1) {
    __shared__ float sW[HID * OUT_C];
    __shared__ float sb1[HID];
    __shared__ float sh[8][HID];
    for (int i = threadIdx.x; i < HID * OUT_C; i += 256) sW[i] = W2[i];
    for (int i = threadIdx.x; i < HID; i += 256) sb1[i] = b1[i];
    __syncthreads();

    int warp = threadIdx.x >> 5, lane = threadIdx.x & 31;
    int node = blockIdx.x * 8 + warp;
    if (node >= N_NODES) return;

    float dv = g_dinv[node];
    float h = fmaxf(g_acc1[(size_t)node * HID + lane] * dv + sb1[lane], 0.0f);
    sh[warp][lane] = h;
    __syncwarp();

    if (lane < OUT_C) {
        float acc = 0.0f;
#pragma unroll
        for (int k = 0; k < HID; k++)
            acc = fmaf(sh[warp][k], sW[k * OUT_C + lane], acc);
        g_g2[(size_t)node * OUT_C + lane] = acc * dv;
    }
}

// K5: layer-2 scatter. 4 threads/edge, float4 + red.v4.
__global__ __launch_bounds__(256) void k_scat2() {
    int t = blockIdx.x * blockDim.x + threadIdx.x;
    if (t >= N_EDGES * 4) return;
    int e = t >> 2, q = t & 3;
    int r = g_row[e];
    int c = g_col[e];
    const float4 v = *(const float4*)(g_g2 + (size_t)r * OUT_C + q * 4);
    float* dst = g_acc2 + (size_t)c * OUT_C + q * 4;
    asm volatile("red.global.add.v4.f32 [%0], {%1,%2,%3,%4};"
                 :: "l"(dst), "f"(v.x), "f"(v.y), "f"(v.z), "f"(v.w) : "memory");
}

// K6: out = acc2*dinv + b2; zero-fill tail (tuple scalar slot).
__global__ void k_final(float* __restrict__ out, const float* __restrict__ b2,
                        int out_size) {
    int t = blockIdx.x * blockDim.x + threadIdx.x;
    if (t >= out_size) return;
    if (t < N_NODES * OUT_C) {
        int c = t >> 4, j = t & 15;         // OUT_C == 16
        out[t] = g_acc2[t] * g_dinv[c] + b2[j];
    } else {
        out[t] = 0.0f;
    }
}

// ---------------------------------------------------------------------------
extern "C" void kernel_launch(void* const* d_in, const int* in_sizes, int n_in,
                              void* d_out, int out_size) {
    const float* x  = (const float*)d_in[0];
    const void*  ei = d_in[1];
    const float* W1 = (const float*)d_in[2];
    const float* b1 = (const float*)d_in[3];
    const float* W2 = (const float*)d_in[4];
    const float* b2 = (const float*)d_in[5];
    float* out = (float*)d_out;

    void *p_degi, *p_acc1, *p_acc2;
    cudaGetSymbolAddress(&p_degi, g_degi);
    cudaGetSymbolAddress(&p_acc1, g_acc1);
    cudaGetSymbolAddress(&p_acc2, g_acc2);
    cudaMemsetAsync(p_degi, 0, (size_t)N_NODES * sizeof(int));
    cudaMemsetAsync(p_acc1, 0, (size_t)N_NODES * HID * sizeof(float));
    cudaMemsetAsync(p_acc2, 0, (size_t)N_NODES * OUT_C * sizeof(float));

    k_detect<<<1, 256>>>(ei);
    k_fusedA<<<GEMM_BLOCKS + DEG_BLOCKS, 256>>>(x, W1, ei);
    k_scale <<<(N_NODES * HID + 255) / 256, 256>>>();
    k_scat1 <<<(N_EDGES * 8) / 256, 256>>>();
    k_fuse  <<<(N_NODES + 7) / 8, 256>>>(W2, b1);
    k_scat2 <<<(N_EDGES * 4) / 256, 256>>>();
    k_final <<<(out_size + 255) / 256, 256>>>(out, b2, out_size);
}